// round 7
// baseline (speedup 1.0000x reference)
#include <cuda_runtime.h>
#include <cuda_bf16.h>
#include <math.h>

#define N_NODES 50000
#define E_NUM   800000
#define IN_F    256
#define HEADS   4
#define DHEAD   64
#define HD      256            // HEADS*DHEAD
#define ALPHA_C 100.0f
#define SLOPE_ATTN 0.2f
#define SLOPE_EW   0.01f

// ---------------- scratch (device globals; allocation-free) ----------------
__device__ float  g_ft[(size_t)N_NODES * HD];      // 51.2 MB
__device__ float  g_el[N_NODES * HEADS];
__device__ float  g_er[N_NODES * HEADS];
__device__ int    g_deg[N_NODES];
__device__ int    g_off[N_NODES + 1];
__device__ int    g_cur[N_NODES];
__device__ int    g_ssrc[E_NUM];
__device__ float4 g_se4[E_NUM];                    // per-edge logits, [p][h] packed

// ---------------- 1) SGEMM: ft = feat @ fc_w^T  (M=50000, N=256, K=256) ----
__global__ __launch_bounds__(256, 2)
void gemm_kernel(const float* __restrict__ A, const float* __restrict__ W) {
    __shared__ float As[8][128];
    __shared__ float Bs[8][128];
    const int tid = threadIdx.x;
    const int bm = blockIdx.y, bn = blockIdx.x;
    const int tx = tid & 15, ty = tid >> 4;
    const int arow = tid >> 1;          // 0..127
    const int acol = (tid & 1) * 4;     // 0 or 4
    const int grow = bm * 128 + arow;   // A row (node)
    const bool aok = grow < N_NODES;
    const int orow = bn * 128 + arow;   // W row (output feature), always < 256

    float acc[8][8];
    #pragma unroll
    for (int i = 0; i < 8; i++)
        #pragma unroll
        for (int j = 0; j < 8; j++) acc[i][j] = 0.f;

    for (int k0 = 0; k0 < IN_F; k0 += 8) {
        float4 av = aok ? *(const float4*)(A + (size_t)grow * IN_F + k0 + acol)
                        : make_float4(0.f, 0.f, 0.f, 0.f);
        float4 bv = *(const float4*)(W + (size_t)orow * IN_F + k0 + acol);
        As[acol + 0][arow] = av.x; As[acol + 1][arow] = av.y;
        As[acol + 2][arow] = av.z; As[acol + 3][arow] = av.w;
        Bs[acol + 0][arow] = bv.x; Bs[acol + 1][arow] = bv.y;
        Bs[acol + 2][arow] = bv.z; Bs[acol + 3][arow] = bv.w;
        __syncthreads();
        #pragma unroll
        for (int kk = 0; kk < 8; kk++) {
            float a[8], b[8];
            #pragma unroll
            for (int i = 0; i < 8; i++) a[i] = As[kk][ty * 8 + i];
            #pragma unroll
            for (int j = 0; j < 8; j++) b[j] = Bs[kk][tx * 8 + j];
            #pragma unroll
            for (int i = 0; i < 8; i++)
                #pragma unroll
                for (int j = 0; j < 8; j++) acc[i][j] += a[i] * b[j];
        }
        __syncthreads();
    }
    #pragma unroll
    for (int i = 0; i < 8; i++) {
        int r = bm * 128 + ty * 8 + i;
        if (r < N_NODES) {
            float* p = g_ft + (size_t)r * HD + bn * 128 + tx * 8;
            float4 v0 = make_float4(acc[i][0], acc[i][1], acc[i][2], acc[i][3]);
            float4 v1 = make_float4(acc[i][4], acc[i][5], acc[i][6], acc[i][7]);
            *(float4*)p = v0;
            *((float4*)p + 1) = v1;
        }
    }
}

// ---------------- 2) el/er: per-(node,head) dot with attn vectors ----------
__global__ void elr_kernel(const float* __restrict__ al, const float* __restrict__ ar) {
    int g = blockIdx.x * blockDim.x + threadIdx.x;
    int node = g >> 6;
    if (node >= N_NODES) return;
    int t = g & 63;
    int h = t >> 4, q = t & 15;
    float4 f  = *(const float4*)(g_ft + (size_t)node * HD + h * DHEAD + q * 4);
    float4 l4 = *(const float4*)(al + h * DHEAD + q * 4);
    float4 r4 = *(const float4*)(ar + h * DHEAD + q * 4);
    float dl = f.x * l4.x + f.y * l4.y + f.z * l4.z + f.w * l4.w;
    float dr = f.x * r4.x + f.y * r4.y + f.z * r4.z + f.w * r4.w;
    #pragma unroll
    for (int o = 8; o; o >>= 1) {
        dl += __shfl_xor_sync(0xffffffff, dl, o);
        dr += __shfl_xor_sync(0xffffffff, dr, o);
    }
    if (q == 0) {
        g_el[node * HEADS + h] = dl;
        g_er[node * HEADS + h] = dr;
    }
}

// ---------------- 3) CSR build: zero, histogram, scan, scatter -------------
__global__ void zero_deg_kernel() {
    int i = blockIdx.x * blockDim.x + threadIdx.x;
    if (i < N_NODES) g_deg[i] = 0;
}

__global__ void hist_kernel(const int* __restrict__ dst) {
    int e = blockIdx.x * blockDim.x + threadIdx.x;
    if (e < E_NUM) atomicAdd(&g_deg[dst[e]], 1);
}

__global__ void scan_kernel() {
    __shared__ int sh[1024];
    __shared__ int carry;
    if (threadIdx.x == 0) carry = 0;
    __syncthreads();
    for (int base = 0; base < N_NODES; base += 1024) {
        int i = base + threadIdx.x;
        int v = (i < N_NODES) ? g_deg[i] : 0;
        sh[threadIdx.x] = v;
        __syncthreads();
        #pragma unroll
        for (int o = 1; o < 1024; o <<= 1) {
            int t = (threadIdx.x >= o) ? sh[threadIdx.x - o] : 0;
            __syncthreads();
            sh[threadIdx.x] += t;
            __syncthreads();
        }
        int excl = sh[threadIdx.x] - v + carry;
        if (i < N_NODES) { g_off[i] = excl; g_cur[i] = excl; }
        __syncthreads();
        if (threadIdx.x == 1023) carry += sh[1023];
        __syncthreads();
    }
    if (threadIdx.x == 0) g_off[N_NODES] = carry;
}

__global__ void scatter_kernel(const int* __restrict__ src, const int* __restrict__ dst,
                               const int* __restrict__ ef, const float* __restrict__ ew) {
    int e = blockIdx.x * blockDim.x + threadIdx.x;
    if (e >= E_NUM) return;
    int s = src[e], d = dst[e], t = ef[e] - 1;
    int p = atomicAdd(&g_cur[d], 1);
    g_ssrc[p] = s;
    float v[HEADS];
    #pragma unroll
    for (int h = 0; h < HEADS; h++) {
        float w = ew[t * HEADS + h] * ALPHA_C;
        w = (w >= 0.f) ? w : SLOPE_EW * w;
        float x = (g_el[s * HEADS + h] + g_er[d * HEADS + h]) * w;
        v[h] = (x >= 0.f) ? x : SLOPE_ATTN * x;
    }
    g_se4[p] = make_float4(v[0], v[1], v[2], v[3]);
}

// ---------------- 4) per-(node,head)-warp softmax + weighted gather --------
__global__ __launch_bounds__(256)
void agg_kernel(float* __restrict__ out) {
    int w = (blockIdx.x * blockDim.x + threadIdx.x) >> 5;
    int lane = threadIdx.x & 31;
    if (w >= N_NODES * HEADS) return;
    int n = w >> 2, h = w & 3;
    int s0 = g_off[n], s1 = g_off[n + 1];
    const float* se = (const float*)g_se4;   // logit of edge k, head h at [k*4+h]

    // pass 1: segment max
    float m = -INFINITY;
    for (int k = s0 + lane; k < s1; k += 32) m = fmaxf(m, se[k * 4 + h]);
    #pragma unroll
    for (int o = 16; o; o >>= 1) m = fmaxf(m, __shfl_xor_sync(0xffffffff, m, o));

    // pass 2: exp weights + weighted gather of ft[src]
    float sum = 0.f, ax = 0.f, ay = 0.f;
    int col = h * DHEAD + lane * 2;
    #pragma unroll 4
    for (int k = s0; k < s1; k++) {
        float wg = __expf(se[k * 4 + h] - m);  // broadcast load, same value all lanes
        int s = g_ssrc[k];                     // broadcast load
        float2 v = *(const float2*)(g_ft + (size_t)s * HD + col);
        ax += wg * v.x;
        ay += wg * v.y;
        sum += wg;
    }
    float inv = (s1 > s0) ? 1.f / sum : 0.f;
    float2 o2 = make_float2(ax * inv, ay * inv);
    *(float2*)(out + (size_t)n * HD + col) = o2;
}

// ---------------- launch --------------------------------------------------
extern "C" void kernel_launch(void* const* d_in, const int* in_sizes, int n_in,
                              void* d_out, int out_size) {
    const float* feat  = (const float*)d_in[0];
    const int*   src   = (const int*)d_in[1];
    const int*   dst   = (const int*)d_in[2];
    const int*   ef    = (const int*)d_in[3];
    const float* fc_w  = (const float*)d_in[4];
    const float* attnl = (const float*)d_in[5];
    const float* attnr = (const float*)d_in[6];
    const float* ew    = (const float*)d_in[7];
    float* out = (float*)d_out;

    (void)in_sizes; (void)n_in; (void)out_size;

    // 1) GEMM
    dim3 ggrid(HD / 128, (N_NODES + 127) / 128);
    gemm_kernel<<<ggrid, 256>>>(feat, fc_w);

    // 2) el / er
    {
        long long tt = (long long)N_NODES * 64;
        elr_kernel<<<(unsigned)((tt + 255) / 256), 256>>>(attnl, attnr);
    }

    // 3) CSR build
    zero_deg_kernel<<<(N_NODES + 255) / 256, 256>>>();
    hist_kernel<<<(E_NUM + 255) / 256, 256>>>(dst);
    scan_kernel<<<1, 1024>>>();
    scatter_kernel<<<(E_NUM + 255) / 256, 256>>>(src, dst, ef, ew);

    // 4) softmax + aggregation (writes the full output, including zeros for
    //    isolated nodes)
    {
        long long tt = (long long)N_NODES * HEADS * 32;
        agg_kernel<<<(unsigned)((tt + 255) / 256), 256>>>(out);
    }
}

// round 10
// speedup vs baseline: 1.2624x; 1.2624x over previous
#include <cuda_runtime.h>
#include <cuda_bf16.h>
#include <math.h>

#define N_NODES 50000
#define E_NUM   800000
#define IN_F    256
#define HEADS   4
#define DHEAD   64
#define HD      256            // HEADS*DHEAD
#define ALPHA_C 100.0f
#define SLOPE_ATTN 0.2f
#define SLOPE_EW   0.01f

// ---------------- scratch (device globals; allocation-free) ----------------
__device__ float  g_ft[(size_t)N_NODES * HD];      // 51.2 MB
__device__ float  g_el[N_NODES * HEADS];
__device__ float  g_er[N_NODES * HEADS];
__device__ int    g_deg[N_NODES];
__device__ int    g_off[N_NODES + 1];
__device__ int    g_cur[N_NODES];
__device__ int    g_ssrc[E_NUM];
__device__ float4 g_se4[E_NUM];                    // per-edge logits, [p][h] packed

// ---------------- helpers --------------------------------------------------
__device__ __forceinline__ float to_tf32(float x) {
    float r;
    asm("cvt.rna.tf32.f32 %0, %1;" : "=f"(r) : "f"(x));
    return r;
}

__device__ __forceinline__ void mma_tf32(float c[4], const unsigned a[4],
                                         const unsigned b[2]) {
    asm volatile(
        "mma.sync.aligned.m16n8k8.row.col.f32.tf32.tf32.f32 "
        "{%0,%1,%2,%3}, {%4,%5,%6,%7}, {%8,%9}, {%0,%1,%2,%3};"
        : "+f"(c[0]), "+f"(c[1]), "+f"(c[2]), "+f"(c[3])
        : "r"(a[0]), "r"(a[1]), "r"(a[2]), "r"(a[3]), "r"(b[0]), "r"(b[1]));
}

// ---------------- 1) tf32 MMA GEMM: ft = feat @ fc_w^T ---------------------
// M=50000, N=256 (=HD), K=256. Block tile 128x128, K-tile 32.
// 8 warps: warp_m in {0,1} (64 rows), warp_n in {0..3} (32 cols).
// Per warp: 4 m-tiles x 4 n-tiles of m16n8k8.
__global__ __launch_bounds__(256, 2)
void gemm_tf32_kernel(const float* __restrict__ A, const float* __restrict__ W) {
    __shared__ float As[32][132];   // [k][m], stride 132 -> bank = (4k+m)%32
    __shared__ float Bs[32][132];   // [k][n]
    const int tid  = threadIdx.x;
    const int bm   = blockIdx.y, bn = blockIdx.x;
    const int lane = tid & 31;
    const int warp = tid >> 5;
    const int warp_m = warp & 1;        // 64-row half
    const int warp_n = warp >> 1;       // 32-col quarter
    const int gid = lane >> 2;          // 0..7
    const int tig = lane & 3;           // 0..3

    const int lrow = tid >> 1;          // 0..127 (tile row this thread loads)
    const int lc4  = (tid & 1) * 16;    // k sub-offset 0 or 16
    const int arow = bm * 128 + lrow;
    const bool aok = arow < N_NODES;
    const float* aptr = A + (size_t)(aok ? arow : 0) * IN_F;
    const float* bptr = W + (size_t)(bn * 128 + lrow) * IN_F;

    float acc[4][4][4];
    #pragma unroll
    for (int im = 0; im < 4; im++)
        #pragma unroll
        for (int in = 0; in < 4; in++)
            #pragma unroll
            for (int q = 0; q < 4; q++) acc[im][in][q] = 0.f;

    for (int k0 = 0; k0 < IN_F; k0 += 32) {
        // stage A,B tiles transposed into smem, tf32-rounded
        #pragma unroll
        for (int j = 0; j < 4; j++) {
            int c = lc4 + j * 4;
            float4 av = *(const float4*)(aptr + k0 + c);
            if (!aok) av = make_float4(0.f, 0.f, 0.f, 0.f);
            float4 bv = *(const float4*)(bptr + k0 + c);
            As[c + 0][lrow] = to_tf32(av.x);
            As[c + 1][lrow] = to_tf32(av.y);
            As[c + 2][lrow] = to_tf32(av.z);
            As[c + 3][lrow] = to_tf32(av.w);
            Bs[c + 0][lrow] = to_tf32(bv.x);
            Bs[c + 1][lrow] = to_tf32(bv.y);
            Bs[c + 2][lrow] = to_tf32(bv.z);
            Bs[c + 3][lrow] = to_tf32(bv.w);
        }
        __syncthreads();

        #pragma unroll
        for (int ks = 0; ks < 4; ks++) {
            const int kb = ks * 8;
            unsigned af[4][4], bf[4][2];
            #pragma unroll
            for (int im = 0; im < 4; im++) {
                int m0 = warp_m * 64 + im * 16;
                af[im][0] = __float_as_uint(As[kb + tig    ][m0 + gid    ]);
                af[im][1] = __float_as_uint(As[kb + tig    ][m0 + gid + 8]);
                af[im][2] = __float_as_uint(As[kb + tig + 4][m0 + gid    ]);
                af[im][3] = __float_as_uint(As[kb + tig + 4][m0 + gid + 8]);
            }
            #pragma unroll
            for (int in = 0; in < 4; in++) {
                int n0 = warp_n * 32 + in * 8;
                bf[in][0] = __float_as_uint(Bs[kb + tig    ][n0 + gid]);
                bf[in][1] = __float_as_uint(Bs[kb + tig + 4][n0 + gid]);
            }
            #pragma unroll
            for (int im = 0; im < 4; im++)
                #pragma unroll
                for (int in = 0; in < 4; in++)
                    mma_tf32(acc[im][in], af[im], bf[in]);
        }
        __syncthreads();
    }

    // epilogue: c0,c1 -> (row, col..col+1); c2,c3 -> (row+8, ...)
    #pragma unroll
    for (int im = 0; im < 4; im++) {
        int r0 = bm * 128 + warp_m * 64 + im * 16 + gid;
        #pragma unroll
        for (int in = 0; in < 4; in++) {
            int cb = bn * 128 + warp_n * 32 + in * 8 + tig * 2;
            if (r0 < N_NODES)
                *(float2*)(g_ft + (size_t)r0 * HD + cb) =
                    make_float2(acc[im][in][0], acc[im][in][1]);
            if (r0 + 8 < N_NODES)
                *(float2*)(g_ft + (size_t)(r0 + 8) * HD + cb) =
                    make_float2(acc[im][in][2], acc[im][in][3]);
        }
    }
}

// ---------------- 2) el/er: per-(node,head) dot with attn vectors ----------
__global__ void elr_kernel(const float* __restrict__ al, const float* __restrict__ ar) {
    int g = blockIdx.x * blockDim.x + threadIdx.x;
    int node = g >> 6;
    if (node >= N_NODES) return;
    int t = g & 63;
    int h = t >> 4, q = t & 15;
    float4 f  = *(const float4*)(g_ft + (size_t)node * HD + h * DHEAD + q * 4);
    float4 l4 = *(const float4*)(al + h * DHEAD + q * 4);
    float4 r4 = *(const float4*)(ar + h * DHEAD + q * 4);
    float dl = f.x * l4.x + f.y * l4.y + f.z * l4.z + f.w * l4.w;
    float dr = f.x * r4.x + f.y * r4.y + f.z * r4.z + f.w * r4.w;
    #pragma unroll
    for (int o = 8; o; o >>= 1) {
        dl += __shfl_xor_sync(0xffffffff, dl, o);
        dr += __shfl_xor_sync(0xffffffff, dr, o);
    }
    if (q == 0) {
        g_el[node * HEADS + h] = dl;
        g_er[node * HEADS + h] = dr;
    }
}

// ---------------- 3) CSR build: zero, histogram, scan, scatter -------------
__global__ void zero_deg_kernel() {
    int i = blockIdx.x * blockDim.x + threadIdx.x;
    if (i < N_NODES) g_deg[i] = 0;
}

__global__ void hist_kernel(const int* __restrict__ dst) {
    int e = blockIdx.x * blockDim.x + threadIdx.x;
    if (e < E_NUM) atomicAdd(&g_deg[dst[e]], 1);
}

__global__ void scan_kernel() {
    __shared__ int sh[1024];
    __shared__ int carry;
    if (threadIdx.x == 0) carry = 0;
    __syncthreads();
    for (int base = 0; base < N_NODES; base += 1024) {
        int i = base + threadIdx.x;
        int v = (i < N_NODES) ? g_deg[i] : 0;
        sh[threadIdx.x] = v;
        __syncthreads();
        #pragma unroll
        for (int o = 1; o < 1024; o <<= 1) {
            int t = (threadIdx.x >= o) ? sh[threadIdx.x - o] : 0;
            __syncthreads();
            sh[threadIdx.x] += t;
            __syncthreads();
        }
        int excl = sh[threadIdx.x] - v + carry;
        if (i < N_NODES) { g_off[i] = excl; g_cur[i] = excl; }
        __syncthreads();
        if (threadIdx.x == 1023) carry += sh[1023];
        __syncthreads();
    }
    if (threadIdx.x == 0) g_off[N_NODES] = carry;
}

__global__ void scatter_kernel(const int* __restrict__ src, const int* __restrict__ dst,
                               const int* __restrict__ ef, const float* __restrict__ ew) {
    int e = blockIdx.x * blockDim.x + threadIdx.x;
    if (e >= E_NUM) return;
    int s = src[e], d = dst[e], t = ef[e] - 1;
    int p = atomicAdd(&g_cur[d], 1);
    g_ssrc[p] = s;
    float v[HEADS];
    #pragma unroll
    for (int h = 0; h < HEADS; h++) {
        float w = ew[t * HEADS + h] * ALPHA_C;
        w = (w >= 0.f) ? w : SLOPE_EW * w;
        float x = (g_el[s * HEADS + h] + g_er[d * HEADS + h]) * w;
        v[h] = (x >= 0.f) ? x : SLOPE_ATTN * x;
    }
    g_se4[p] = make_float4(v[0], v[1], v[2], v[3]);
}

// ---------------- 4) per-(node,head)-warp softmax + weighted gather --------
__global__ __launch_bounds__(256)
void agg_kernel(float* __restrict__ out) {
    int w = (blockIdx.x * blockDim.x + threadIdx.x) >> 5;
    int lane = threadIdx.x & 31;
    if (w >= N_NODES * HEADS) return;
    int n = w >> 2, h = w & 3;
    int s0 = g_off[n], s1 = g_off[n + 1];
    const float* se = (const float*)g_se4;   // logit of edge k, head h at [k*4+h]

    // pass 1: segment max
    float m = -INFINITY;
    for (int k = s0 + lane; k < s1; k += 32) m = fmaxf(m, se[k * 4 + h]);
    #pragma unroll
    for (int o = 16; o; o >>= 1) m = fmaxf(m, __shfl_xor_sync(0xffffffff, m, o));

    // pass 2: exp weights + weighted gather of ft[src]
    float sum = 0.f, ax = 0.f, ay = 0.f;
    int col = h * DHEAD + lane * 2;
    #pragma unroll 4
    for (int k = s0; k < s1; k++) {
        float wg = __expf(se[k * 4 + h] - m);  // broadcast load, same value all lanes
        int s = g_ssrc[k];                     // broadcast load
        float2 v = *(const float2*)(g_ft + (size_t)s * HD + col);
        ax += wg * v.x;
        ay += wg * v.y;
        sum += wg;
    }
    float inv = (s1 > s0) ? 1.f / sum : 0.f;
    float2 o2 = make_float2(ax * inv, ay * inv);
    *(float2*)(out + (size_t)n * HD + col) = o2;
}

// ---------------- launch --------------------------------------------------
extern "C" void kernel_launch(void* const* d_in, const int* in_sizes, int n_in,
                              void* d_out, int out_size) {
    const float* feat  = (const float*)d_in[0];
    const int*   src   = (const int*)d_in[1];
    const int*   dst   = (const int*)d_in[2];
    const int*   ef    = (const int*)d_in[3];
    const float* fc_w  = (const float*)d_in[4];
    const float* attnl = (const float*)d_in[5];
    const float* attnr = (const float*)d_in[6];
    const float* ew    = (const float*)d_in[7];
    float* out = (float*)d_out;

    (void)in_sizes; (void)n_in; (void)out_size;

    // 1) GEMM (tf32 tensor-core)
    dim3 ggrid(HD / 128, (N_NODES + 127) / 128);
    gemm_tf32_kernel<<<ggrid, 256>>>(feat, fc_w);

    // 2) el / er
    {
        long long tt = (long long)N_NODES * 64;
        elr_kernel<<<(unsigned)((tt + 255) / 256), 256>>>(attnl, attnr);
    }

    // 3) CSR build
    zero_deg_kernel<<<(N_NODES + 255) / 256, 256>>>();
    hist_kernel<<<(E_NUM + 255) / 256, 256>>>(dst);
    scan_kernel<<<1, 1024>>>();
    scatter_kernel<<<(E_NUM + 255) / 256, 256>>>(src, dst, ef, ew);

    // 4) softmax + aggregation
    {
        long long tt = (long long)N_NODES * HEADS * 32;
        agg_kernel<<<(unsigned)((tt + 255) / 256), 256>>>(out);
    }
}

// round 11
// speedup vs baseline: 1.6600x; 1.3149x over previous
#include <cuda_runtime.h>
#include <cuda_bf16.h>
#include <math.h>

#define N_NODES 50000
#define E_NUM   800000
#define IN_F    256
#define HEADS   4
#define DHEAD   64
#define HD      256            // HEADS*DHEAD
#define ALPHA_C 100.0f
#define SLOPE_ATTN 0.2f
#define SLOPE_EW   0.01f

#define SCAN_B  1024
#define SCAN_NB ((N_NODES + SCAN_B - 1) / SCAN_B)   // 49

// ---------------- scratch (device globals; allocation-free) ----------------
__device__ float  g_ft[(size_t)N_NODES * HD];      // 51.2 MB
__device__ float  g_el[N_NODES * HEADS];
__device__ float  g_er[N_NODES * HEADS];
__device__ int    g_deg[N_NODES];
__device__ int    g_off[N_NODES + 1];
__device__ int    g_cur[N_NODES];
__device__ int    g_ssrc[E_NUM];
__device__ float4 g_se4[E_NUM];                    // per-edge logits, [p][h] packed
__device__ int    g_bsum[SCAN_NB];

// ---------------- helpers --------------------------------------------------
__device__ __forceinline__ float to_tf32(float x) {
    float r;
    asm("cvt.rna.tf32.f32 %0, %1;" : "=f"(r) : "f"(x));
    return r;
}

__device__ __forceinline__ void mma_tf32(float c[4], const unsigned a[4],
                                         const unsigned b[2]) {
    asm volatile(
        "mma.sync.aligned.m16n8k8.row.col.f32.tf32.tf32.f32 "
        "{%0,%1,%2,%3}, {%4,%5,%6,%7}, {%8,%9}, {%0,%1,%2,%3};"
        : "+f"(c[0]), "+f"(c[1]), "+f"(c[2]), "+f"(c[3])
        : "r"(a[0]), "r"(a[1]), "r"(a[2]), "r"(a[3]), "r"(b[0]), "r"(b[1]));
}

// ---------------- 1) tf32 MMA GEMM, double-buffered ------------------------
// M=50000, N=256, K=256. Block tile 128x128, K-tile 16, 2-stage smem pipeline.
// 8 warps: warp_m in {0,1} (64 rows), warp_n in {0..3} (32 cols).
__global__ __launch_bounds__(256, 2)
void gemm_tf32_kernel(const float* __restrict__ A, const float* __restrict__ W) {
    __shared__ float As[2][16][132];   // [buf][k][m]; bank(frag) = (4*tig+gid)%32, CF
    __shared__ float Bs[2][16][132];   // [buf][k][n]
    const int tid  = threadIdx.x;
    const int bm   = blockIdx.y, bn = blockIdx.x;
    const int lane = tid & 31;
    const int warp = tid >> 5;
    const int warp_m = warp & 1;
    const int warp_n = warp >> 1;
    const int gid = lane >> 2;          // 0..7
    const int tig = lane & 3;           // 0..3

    const int lrow = tid >> 1;          // 0..127
    const int lc   = (tid & 1) * 8;     // k sub-offset 0 or 8
    const int arow = bm * 128 + lrow;
    const bool aok = arow < N_NODES;
    const float* aptr = A + (size_t)(aok ? arow : 0) * IN_F + lc;
    const float* bptr = W + (size_t)(bn * 128 + lrow) * IN_F + lc;

    float acc[4][4][4];
    #pragma unroll
    for (int im = 0; im < 4; im++)
        #pragma unroll
        for (int in = 0; in < 4; in++)
            #pragma unroll
            for (int q = 0; q < 4; q++) acc[im][in][q] = 0.f;

    float4 ra[2], rb[2];
    // prefetch k-tile 0
    #pragma unroll
    for (int j = 0; j < 2; j++) {
        ra[j] = aok ? *(const float4*)(aptr + j * 4) : make_float4(0.f, 0.f, 0.f, 0.f);
        rb[j] = *(const float4*)(bptr + j * 4);
    }
    // stage into buf 0
    #pragma unroll
    for (int j = 0; j < 2; j++) {
        const float* av = (const float*)&ra[j];
        const float* bv = (const float*)&rb[j];
        #pragma unroll
        for (int i = 0; i < 4; i++) {
            As[0][lc + j * 4 + i][lrow] = to_tf32(av[i]);
            Bs[0][lc + j * 4 + i][lrow] = to_tf32(bv[i]);
        }
    }
    __syncthreads();

    const int NKT = IN_F / 16;   // 16
    for (int kt = 0; kt < NKT; kt++) {
        const int buf = kt & 1;
        // prefetch next k-tile into registers (LDG in flight during compute)
        if (kt + 1 < NKT) {
            #pragma unroll
            for (int j = 0; j < 2; j++) {
                ra[j] = aok ? *(const float4*)(aptr + (kt + 1) * 16 + j * 4)
                            : make_float4(0.f, 0.f, 0.f, 0.f);
                rb[j] = *(const float4*)(bptr + (kt + 1) * 16 + j * 4);
            }
        }
        // compute current tile
        #pragma unroll
        for (int ks = 0; ks < 2; ks++) {
            const int kb = ks * 8;
            unsigned af[4][4], bf[4][2];
            #pragma unroll
            for (int im = 0; im < 4; im++) {
                int m0 = warp_m * 64 + im * 16;
                af[im][0] = __float_as_uint(As[buf][kb + tig    ][m0 + gid    ]);
                af[im][1] = __float_as_uint(As[buf][kb + tig    ][m0 + gid + 8]);
                af[im][2] = __float_as_uint(As[buf][kb + tig + 4][m0 + gid    ]);
                af[im][3] = __float_as_uint(As[buf][kb + tig + 4][m0 + gid + 8]);
            }
            #pragma unroll
            for (int in = 0; in < 4; in++) {
                int n0 = warp_n * 32 + in * 8;
                bf[in][0] = __float_as_uint(Bs[buf][kb + tig    ][n0 + gid]);
                bf[in][1] = __float_as_uint(Bs[buf][kb + tig + 4][n0 + gid]);
            }
            #pragma unroll
            for (int im = 0; im < 4; im++)
                #pragma unroll
                for (int in = 0; in < 4; in++)
                    mma_tf32(acc[im][in], af[im], bf[in]);
        }
        // stage next tile into the other buffer
        if (kt + 1 < NKT) {
            #pragma unroll
            for (int j = 0; j < 2; j++) {
                const float* av = (const float*)&ra[j];
                const float* bv = (const float*)&rb[j];
                #pragma unroll
                for (int i = 0; i < 4; i++) {
                    As[buf ^ 1][lc + j * 4 + i][lrow] = to_tf32(av[i]);
                    Bs[buf ^ 1][lc + j * 4 + i][lrow] = to_tf32(bv[i]);
                }
            }
            __syncthreads();
        }
    }

    // epilogue
    #pragma unroll
    for (int im = 0; im < 4; im++) {
        int r0 = bm * 128 + warp_m * 64 + im * 16 + gid;
        #pragma unroll
        for (int in = 0; in < 4; in++) {
            int cb = bn * 128 + warp_n * 32 + in * 8 + tig * 2;
            if (r0 < N_NODES)
                *(float2*)(g_ft + (size_t)r0 * HD + cb) =
                    make_float2(acc[im][in][0], acc[im][in][1]);
            if (r0 + 8 < N_NODES)
                *(float2*)(g_ft + (size_t)(r0 + 8) * HD + cb) =
                    make_float2(acc[im][in][2], acc[im][in][3]);
        }
    }
}

// ---------------- 2) el/er: per-(node,head) dot with attn vectors ----------
__global__ void elr_kernel(const float* __restrict__ al, const float* __restrict__ ar) {
    int g = blockIdx.x * blockDim.x + threadIdx.x;
    int node = g >> 6;
    if (node >= N_NODES) return;
    int t = g & 63;
    int h = t >> 4, q = t & 15;
    float4 f  = *(const float4*)(g_ft + (size_t)node * HD + h * DHEAD + q * 4);
    float4 l4 = *(const float4*)(al + h * DHEAD + q * 4);
    float4 r4 = *(const float4*)(ar + h * DHEAD + q * 4);
    float dl = f.x * l4.x + f.y * l4.y + f.z * l4.z + f.w * l4.w;
    float dr = f.x * r4.x + f.y * r4.y + f.z * r4.z + f.w * r4.w;
    #pragma unroll
    for (int o = 8; o; o >>= 1) {
        dl += __shfl_xor_sync(0xffffffff, dl, o);
        dr += __shfl_xor_sync(0xffffffff, dr, o);
    }
    if (q == 0) {
        g_el[node * HEADS + h] = dl;
        g_er[node * HEADS + h] = dr;
    }
}

// ---------------- 3) CSR build ---------------------------------------------
__global__ void zero_deg_kernel() {
    int i = blockIdx.x * blockDim.x + threadIdx.x;
    if (i < N_NODES) g_deg[i] = 0;
}

__global__ void hist_kernel(const int* __restrict__ dst) {
    int e = blockIdx.x * blockDim.x + threadIdx.x;
    if (e < E_NUM) atomicAdd(&g_deg[dst[e]], 1);
}

// phase 1: per-block exclusive scan (1024 elems), write block sums
__global__ __launch_bounds__(SCAN_B)
void scan1_kernel() {
    __shared__ int ws[32];
    int tid = threadIdx.x, lane = tid & 31, wid = tid >> 5;
    int i = blockIdx.x * SCAN_B + tid;
    int v = (i < N_NODES) ? g_deg[i] : 0;
    int x = v;
    #pragma unroll
    for (int o = 1; o < 32; o <<= 1) {
        int t = __shfl_up_sync(0xffffffff, x, o);
        if (lane >= o) x += t;
    }
    if (lane == 31) ws[wid] = x;
    __syncthreads();
    if (wid == 0) {
        int y = ws[lane];
        #pragma unroll
        for (int o = 1; o < 32; o <<= 1) {
            int t = __shfl_up_sync(0xffffffff, y, o);
            if (lane >= o) y += t;
        }
        ws[lane] = y;
    }
    __syncthreads();
    int base = (wid == 0) ? 0 : ws[wid - 1];
    if (i < N_NODES) g_off[i] = base + x - v;   // block-local exclusive
    if (tid == 0) g_bsum[blockIdx.x] = ws[31];  // block total
}

// phase 2: exclusive scan of SCAN_NB block sums (one block, 64 threads)
__global__ void scan2_kernel() {
    __shared__ int ws[2];
    int tid = threadIdx.x, lane = tid & 31, wid = tid >> 5;
    int v = (tid < SCAN_NB) ? g_bsum[tid] : 0;
    int x = v;
    #pragma unroll
    for (int o = 1; o < 32; o <<= 1) {
        int t = __shfl_up_sync(0xffffffff, x, o);
        if (lane >= o) x += t;
    }
    if (lane == 31) ws[wid] = x;
    __syncthreads();
    int base = (wid == 1) ? ws[0] : 0;
    if (tid < SCAN_NB) g_bsum[tid] = base + x - v;
}

// phase 3: add block offsets, produce g_off/g_cur, and g_off[N]
__global__ void scan3_kernel() {
    int i = blockIdx.x * blockDim.x + threadIdx.x;
    if (i < N_NODES) {
        int off = g_off[i] + g_bsum[i >> 10];
        g_off[i] = off;
        g_cur[i] = off;
    }
    if (i == 0) g_off[N_NODES] = E_NUM;
}

__global__ void scatter_kernel(const int* __restrict__ src, const int* __restrict__ dst,
                               const int* __restrict__ ef, const float* __restrict__ ew) {
    int e = blockIdx.x * blockDim.x + threadIdx.x;
    if (e >= E_NUM) return;
    int s = src[e], d = dst[e], t = ef[e] - 1;
    int p = atomicAdd(&g_cur[d], 1);
    g_ssrc[p] = s;
    float v[HEADS];
    #pragma unroll
    for (int h = 0; h < HEADS; h++) {
        float w = ew[t * HEADS + h] * ALPHA_C;
        w = (w >= 0.f) ? w : SLOPE_EW * w;
        float x = (g_el[s * HEADS + h] + g_er[d * HEADS + h]) * w;
        v[h] = (x >= 0.f) ? x : SLOPE_ATTN * x;
    }
    g_se4[p] = make_float4(v[0], v[1], v[2], v[3]);
}

// ---------------- 4) per-(node,head)-warp softmax + weighted gather --------
__global__ __launch_bounds__(256)
void agg_kernel(float* __restrict__ out) {
    int w = (blockIdx.x * blockDim.x + threadIdx.x) >> 5;
    int lane = threadIdx.x & 31;
    if (w >= N_NODES * HEADS) return;
    int n = w >> 2, h = w & 3;
    int s0 = g_off[n], s1 = g_off[n + 1];
    const float* se = (const float*)g_se4;

    float m = -INFINITY;
    for (int k = s0 + lane; k < s1; k += 32) m = fmaxf(m, se[k * 4 + h]);
    #pragma unroll
    for (int o = 16; o; o >>= 1) m = fmaxf(m, __shfl_xor_sync(0xffffffff, m, o));

    float sum = 0.f, ax = 0.f, ay = 0.f;
    int col = h * DHEAD + lane * 2;
    #pragma unroll 4
    for (int k = s0; k < s1; k++) {
        float wg = __expf(se[k * 4 + h] - m);
        int s = g_ssrc[k];
        float2 v = *(const float2*)(g_ft + (size_t)s * HD + col);
        ax += wg * v.x;
        ay += wg * v.y;
        sum += wg;
    }
    float inv = (s1 > s0) ? 1.f / sum : 0.f;
    *(float2*)(out + (size_t)n * HD + col) = make_float2(ax * inv, ay * inv);
}

// ---------------- launch --------------------------------------------------
extern "C" void kernel_launch(void* const* d_in, const int* in_sizes, int n_in,
                              void* d_out, int out_size) {
    const float* feat  = (const float*)d_in[0];
    const int*   src   = (const int*)d_in[1];
    const int*   dst   = (const int*)d_in[2];
    const int*   ef    = (const int*)d_in[3];
    const float* fc_w  = (const float*)d_in[4];
    const float* attnl = (const float*)d_in[5];
    const float* attnr = (const float*)d_in[6];
    const float* ew    = (const float*)d_in[7];
    float* out = (float*)d_out;

    (void)in_sizes; (void)n_in; (void)out_size;

    // 1) GEMM (tf32 tensor-core, double-buffered)
    dim3 ggrid(HD / 128, (N_NODES + 127) / 128);
    gemm_tf32_kernel<<<ggrid, 256>>>(feat, fc_w);

    // 2) el / er
    {
        long long tt = (long long)N_NODES * 64;
        elr_kernel<<<(unsigned)((tt + 255) / 256), 256>>>(attnl, attnr);
    }

    // 3) CSR build
    zero_deg_kernel<<<(N_NODES + 255) / 256, 256>>>();
    hist_kernel<<<(E_NUM + 255) / 256, 256>>>(dst);
    scan1_kernel<<<SCAN_NB, SCAN_B>>>();
    scan2_kernel<<<1, 64>>>();
    scan3_kernel<<<(N_NODES + 255) / 256, 256>>>();
    scatter_kernel<<<(E_NUM + 255) / 256, 256>>>(src, dst, ef, ew);

    // 4) softmax + aggregation
    {
        long long tt = (long long)N_NODES * HEADS * 32;
        agg_kernel<<<(unsigned)((tt + 255) / 256), 256>>>(out);
    }
}

// round 13
// speedup vs baseline: 2.1621x; 1.3025x over previous
#include <cuda_runtime.h>
#include <cuda_fp16.h>
#include <math.h>

#define N_NODES 50000
#define E_NUM   800000
#define IN_F    256
#define HEADS   4
#define DHEAD   64
#define HD      256            // HEADS*DHEAD
#define ALPHA_C 100.0f
#define SLOPE_ATTN 0.2f
#define SLOPE_EW   0.01f

#define SCAN_B  1024
#define SCAN_NB ((N_NODES + SCAN_B - 1) / SCAN_B)   // 49

// ---------------- scratch (device globals; allocation-free) ----------------
__device__ __half  g_fth[(size_t)N_NODES * HD];    // 25.6 MB, fp16 ft
__device__ float   g_el[N_NODES * HEADS];
__device__ float   g_er[N_NODES * HEADS];
__device__ int     g_deg[N_NODES];
__device__ int     g_off[N_NODES + 1];
__device__ int     g_cur[N_NODES];
__device__ int     g_ssrc[E_NUM];
__device__ float4  g_se4[E_NUM];                   // per-edge logits, [p][h] packed
__device__ int     g_bsum[SCAN_NB];

// ---------------- helpers --------------------------------------------------
__device__ __forceinline__ float to_tf32(float x) {
    float r;
    asm("cvt.rna.tf32.f32 %0, %1;" : "=f"(r) : "f"(x));
    return r;
}

__device__ __forceinline__ void mma_tf32(float c[4], const unsigned a[4],
                                         const unsigned b[2]) {
    asm volatile(
        "mma.sync.aligned.m16n8k8.row.col.f32.tf32.tf32.f32 "
        "{%0,%1,%2,%3}, {%4,%5,%6,%7}, {%8,%9}, {%0,%1,%2,%3};"
        : "+f"(c[0]), "+f"(c[1]), "+f"(c[2]), "+f"(c[3])
        : "r"(a[0]), "r"(a[1]), "r"(a[2]), "r"(a[3]), "r"(b[0]), "r"(b[1]));
}

// ---------------- 1) tf32 MMA GEMM, double-buffered, fp16 output -----------
// M=50000, N=256, K=256. Block tile 128x128, K-tile 16, 2-stage smem pipeline.
__global__ __launch_bounds__(256, 2)
void gemm_tf32_kernel(const float* __restrict__ A, const float* __restrict__ W) {
    __shared__ float As[2][16][132];   // [buf][k][m]
    __shared__ float Bs[2][16][132];   // [buf][k][n]
    const int tid  = threadIdx.x;
    const int bm   = blockIdx.y, bn = blockIdx.x;
    const int lane = tid & 31;
    const int warp = tid >> 5;
    const int warp_m = warp & 1;
    const int warp_n = warp >> 1;
    const int gid = lane >> 2;          // 0..7
    const int tig = lane & 3;           // 0..3

    const int lrow = tid >> 1;          // 0..127
    const int lc   = (tid & 1) * 8;     // k sub-offset 0 or 8
    const int arow = bm * 128 + lrow;
    const bool aok = arow < N_NODES;
    const float* aptr = A + (size_t)(aok ? arow : 0) * IN_F + lc;
    const float* bptr = W + (size_t)(bn * 128 + lrow) * IN_F + lc;

    float acc[4][4][4];
    #pragma unroll
    for (int im = 0; im < 4; im++)
        #pragma unroll
        for (int in = 0; in < 4; in++)
            #pragma unroll
            for (int q = 0; q < 4; q++) acc[im][in][q] = 0.f;

    float4 ra[2], rb[2];
    #pragma unroll
    for (int j = 0; j < 2; j++) {
        ra[j] = aok ? *(const float4*)(aptr + j * 4) : make_float4(0.f, 0.f, 0.f, 0.f);
        rb[j] = *(const float4*)(bptr + j * 4);
    }
    #pragma unroll
    for (int j = 0; j < 2; j++) {
        const float* av = (const float*)&ra[j];
        const float* bv = (const float*)&rb[j];
        #pragma unroll
        for (int i = 0; i < 4; i++) {
            As[0][lc + j * 4 + i][lrow] = to_tf32(av[i]);
            Bs[0][lc + j * 4 + i][lrow] = to_tf32(bv[i]);
        }
    }
    __syncthreads();

    const int NKT = IN_F / 16;   // 16
    for (int kt = 0; kt < NKT; kt++) {
        const int buf = kt & 1;
        if (kt + 1 < NKT) {
            #pragma unroll
            for (int j = 0; j < 2; j++) {
                ra[j] = aok ? *(const float4*)(aptr + (kt + 1) * 16 + j * 4)
                            : make_float4(0.f, 0.f, 0.f, 0.f);
                rb[j] = *(const float4*)(bptr + (kt + 1) * 16 + j * 4);
            }
        }
        #pragma unroll
        for (int ks = 0; ks < 2; ks++) {
            const int kb = ks * 8;
            unsigned af[4][4], bf[4][2];
            #pragma unroll
            for (int im = 0; im < 4; im++) {
                int m0 = warp_m * 64 + im * 16;
                af[im][0] = __float_as_uint(As[buf][kb + tig    ][m0 + gid    ]);
                af[im][1] = __float_as_uint(As[buf][kb + tig    ][m0 + gid + 8]);
                af[im][2] = __float_as_uint(As[buf][kb + tig + 4][m0 + gid    ]);
                af[im][3] = __float_as_uint(As[buf][kb + tig + 4][m0 + gid + 8]);
            }
            #pragma unroll
            for (int in = 0; in < 4; in++) {
                int n0 = warp_n * 32 + in * 8;
                bf[in][0] = __float_as_uint(Bs[buf][kb + tig    ][n0 + gid]);
                bf[in][1] = __float_as_uint(Bs[buf][kb + tig + 4][n0 + gid]);
            }
            #pragma unroll
            for (int im = 0; im < 4; im++)
                #pragma unroll
                for (int in = 0; in < 4; in++)
                    mma_tf32(acc[im][in], af[im], bf[in]);
        }
        if (kt + 1 < NKT) {
            #pragma unroll
            for (int j = 0; j < 2; j++) {
                const float* av = (const float*)&ra[j];
                const float* bv = (const float*)&rb[j];
                #pragma unroll
                for (int i = 0; i < 4; i++) {
                    As[buf ^ 1][lc + j * 4 + i][lrow] = to_tf32(av[i]);
                    Bs[buf ^ 1][lc + j * 4 + i][lrow] = to_tf32(bv[i]);
                }
            }
            __syncthreads();
        }
    }

    // epilogue: fp16 (RTE) stores, half2 per (row, col pair)
    #pragma unroll
    for (int im = 0; im < 4; im++) {
        int r0 = bm * 128 + warp_m * 64 + im * 16 + gid;
        #pragma unroll
        for (int in = 0; in < 4; in++) {
            int cb = bn * 128 + warp_n * 32 + in * 8 + tig * 2;
            if (r0 < N_NODES)
                *(__half2*)(g_fth + (size_t)r0 * HD + cb) =
                    __floats2half2_rn(acc[im][in][0], acc[im][in][1]);
            if (r0 + 8 < N_NODES)
                *(__half2*)(g_fth + (size_t)(r0 + 8) * HD + cb) =
                    __floats2half2_rn(acc[im][in][2], acc[im][in][3]);
        }
    }
}

// ---------------- 2) el/er: warp per node, lane owns 8 cols ----------------
__global__ void elr_kernel(const float* __restrict__ al, const float* __restrict__ ar) {
    int g = blockIdx.x * blockDim.x + threadIdx.x;
    int node = g >> 5;
    if (node >= N_NODES) return;
    int lane = g & 31;
    int h = lane >> 3, q = lane & 7;

    uint4 v = *(const uint4*)(g_fth + (size_t)node * HD + lane * 8);
    const __half2* hv = (const __half2*)&v;
    const float* alp = al + h * DHEAD + q * 8;
    const float* arp = ar + h * DHEAD + q * 8;
    float4 l0 = *(const float4*)(alp), l1 = *(const float4*)(alp + 4);
    float4 r0 = *(const float4*)(arp), r1 = *(const float4*)(arp + 4);
    float f[8];
    #pragma unroll
    for (int j = 0; j < 4; j++) {
        float2 p = __half22float2(hv[j]);
        f[2 * j] = p.x; f[2 * j + 1] = p.y;
    }
    float dl = f[0]*l0.x + f[1]*l0.y + f[2]*l0.z + f[3]*l0.w
             + f[4]*l1.x + f[5]*l1.y + f[6]*l1.z + f[7]*l1.w;
    float dr = f[0]*r0.x + f[1]*r0.y + f[2]*r0.z + f[3]*r0.w
             + f[4]*r1.x + f[5]*r1.y + f[6]*r1.z + f[7]*r1.w;
    #pragma unroll
    for (int o = 4; o; o >>= 1) {
        dl += __shfl_xor_sync(0xffffffff, dl, o);
        dr += __shfl_xor_sync(0xffffffff, dr, o);
    }
    if (q == 0) {
        g_el[node * HEADS + h] = dl;
        g_er[node * HEADS + h] = dr;
    }
}

// ---------------- 3) CSR build ---------------------------------------------
__global__ void zero_deg_kernel() {
    int i = blockIdx.x * blockDim.x + threadIdx.x;
    if (i < N_NODES) g_deg[i] = 0;
}

__global__ void hist_kernel(const int* __restrict__ dst) {
    int e = blockIdx.x * blockDim.x + threadIdx.x;
    if (e < E_NUM) atomicAdd(&g_deg[dst[e]], 1);
}

__global__ __launch_bounds__(SCAN_B)
void scan1_kernel() {
    __shared__ int ws[32];
    int tid = threadIdx.x, lane = tid & 31, wid = tid >> 5;
    int i = blockIdx.x * SCAN_B + tid;
    int v = (i < N_NODES) ? g_deg[i] : 0;
    int x = v;
    #pragma unroll
    for (int o = 1; o < 32; o <<= 1) {
        int t = __shfl_up_sync(0xffffffff, x, o);
        if (lane >= o) x += t;
    }
    if (lane == 31) ws[wid] = x;
    __syncthreads();
    if (wid == 0) {
        int y = ws[lane];
        #pragma unroll
        for (int o = 1; o < 32; o <<= 1) {
            int t = __shfl_up_sync(0xffffffff, y, o);
            if (lane >= o) y += t;
        }
        ws[lane] = y;
    }
    __syncthreads();
    int base = (wid == 0) ? 0 : ws[wid - 1];
    if (i < N_NODES) g_off[i] = base + x - v;
    if (tid == 0) g_bsum[blockIdx.x] = ws[31];
}

__global__ void scan2_kernel() {
    __shared__ int ws[2];
    int tid = threadIdx.x, lane = tid & 31, wid = tid >> 5;
    int v = (tid < SCAN_NB) ? g_bsum[tid] : 0;
    int x = v;
    #pragma unroll
    for (int o = 1; o < 32; o <<= 1) {
        int t = __shfl_up_sync(0xffffffff, x, o);
        if (lane >= o) x += t;
    }
    if (lane == 31) ws[wid] = x;
    __syncthreads();
    int base = (wid == 1) ? ws[0] : 0;
    if (tid < SCAN_NB) g_bsum[tid] = base + x - v;
}

__global__ void scan3_kernel() {
    int i = blockIdx.x * blockDim.x + threadIdx.x;
    if (i < N_NODES) {
        int off = g_off[i] + g_bsum[i >> 10];
        g_off[i] = off;
        g_cur[i] = off;
    }
    if (i == 0) g_off[N_NODES] = E_NUM;
}

__global__ void scatter_kernel(const int* __restrict__ src, const int* __restrict__ dst,
                               const int* __restrict__ ef, const float* __restrict__ ew) {
    int e = blockIdx.x * blockDim.x + threadIdx.x;
    if (e >= E_NUM) return;
    int s = src[e], d = dst[e], t = ef[e] - 1;
    int p = atomicAdd(&g_cur[d], 1);
    g_ssrc[p] = s;
    float v[HEADS];
    #pragma unroll
    for (int h = 0; h < HEADS; h++) {
        float w = ew[t * HEADS + h] * ALPHA_C;
        w = (w >= 0.f) ? w : SLOPE_EW * w;
        float x = (g_el[s * HEADS + h] + g_er[d * HEADS + h]) * w;
        v[h] = (x >= 0.f) ? x : SLOPE_ATTN * x;
    }
    g_se4[p] = make_float4(v[0], v[1], v[2], v[3]);
}

// ---------------- 4) warp per node: softmax + weighted gather, all heads ---
__global__ __launch_bounds__(256)
void agg_kernel(float* __restrict__ out) {
    int n = (blockIdx.x * blockDim.x + threadIdx.x) >> 5;
    int lane = threadIdx.x & 31;
    if (n >= N_NODES) return;
    int h = lane >> 3, q = lane & 7;
    int s0 = g_off[n], s1 = g_off[n + 1];
    const float* se = (const float*)g_se4;   // logit of edge k, head h at [k*4+h]

    // pass 1: per-head max, 8-wide strided + 3-step reduce within head group
    float m = -INFINITY;
    for (int k = s0 + q; k < s1; k += 8) m = fmaxf(m, se[k * 4 + h]);
    #pragma unroll
    for (int o = 4; o; o >>= 1) m = fmaxf(m, __shfl_xor_sync(0xffffffff, m, o));

    // pass 2: exp weights + gather ft[src] (one uint4/lane = 8 halves = full row/warp)
    float sum = 0.f;
    float acc[8];
    #pragma unroll
    for (int j = 0; j < 8; j++) acc[j] = 0.f;
    #pragma unroll 4
    for (int k = s0; k < s1; k++) {
        float wg = __expf(se[k * 4 + h] - m);   // 4B load, 1 sector/warp
        int s = g_ssrc[k];                      // broadcast
        uint4 v = *(const uint4*)(g_fth + (size_t)s * HD + lane * 8);
        const __half2* hv = (const __half2*)&v;
        #pragma unroll
        for (int j = 0; j < 4; j++) {
            float2 p = __half22float2(hv[j]);
            acc[2 * j]     += wg * p.x;
            acc[2 * j + 1] += wg * p.y;
        }
        sum += wg;
    }
    float inv = (s1 > s0) ? 1.f / sum : 0.f;
    float* op = out + (size_t)n * HD + lane * 8;
    *(float4*)op       = make_float4(acc[0] * inv, acc[1] * inv, acc[2] * inv, acc[3] * inv);
    *((float4*)op + 1) = make_float4(acc[4] * inv, acc[5] * inv, acc[6] * inv, acc[7] * inv);
}

// ---------------- launch --------------------------------------------------
extern "C" void kernel_launch(void* const* d_in, const int* in_sizes, int n_in,
                              void* d_out, int out_size) {
    const float* feat  = (const float*)d_in[0];
    const int*   src   = (const int*)d_in[1];
    const int*   dst   = (const int*)d_in[2];
    const int*   ef    = (const int*)d_in[3];
    const float* fc_w  = (const float*)d_in[4];
    const float* attnl = (const float*)d_in[5];
    const float* attnr = (const float*)d_in[6];
    const float* ew    = (const float*)d_in[7];
    float* out = (float*)d_out;

    (void)in_sizes; (void)n_in; (void)out_size;

    // 1) GEMM (tf32 tensor-core, double-buffered, fp16 output)
    dim3 ggrid(HD / 128, (N_NODES + 127) / 128);
    gemm_tf32_kernel<<<ggrid, 256>>>(feat, fc_w);

    // 2) el / er
    {
        long long tt = (long long)N_NODES * 32;
        elr_kernel<<<(unsigned)((tt + 255) / 256), 256>>>(attnl, attnr);
    }

    // 3) CSR build
    zero_deg_kernel<<<(N_NODES + 255) / 256, 256>>>();
    hist_kernel<<<(E_NUM + 255) / 256, 256>>>(dst);
    scan1_kernel<<<SCAN_NB, SCAN_B>>>();
    scan2_kernel<<<1, 64>>>();
    scan3_kernel<<<(N_NODES + 255) / 256, 256>>>();
    scatter_kernel<<<(E_NUM + 255) / 256, 256>>>(src, dst, ef, ew);

    // 4) softmax + aggregation (warp per node, all heads)
    {
        long long tt = (long long)N_NODES * 32;
        agg_kernel<<<(unsigned)((tt + 255) / 256), 256>>>(out);
    }
}

// round 16
// speedup vs baseline: 2.6078x; 1.2061x over previous
#include <cuda_runtime.h>
#include <cuda_fp16.h>
#include <math.h>

#define N_NODES 50000
#define E_NUM   800000
#define IN_F    256
#define HEADS   4
#define DHEAD   64
#define HD      256            // HEADS*DHEAD
#define ALPHA_C 100.0f
#define SLOPE_ATTN 0.2f
#define SLOPE_EW   0.01f

#define SCAN_B  1024
#define SCAN_NB ((N_NODES + SCAN_B - 1) / SCAN_B)   // 49

// ---------------- scratch (device globals; allocation-free) ----------------
__device__ __half  g_fth[(size_t)N_NODES * HD];    // 25.6 MB, fp16 ft
__device__ float   g_el[N_NODES * HEADS];
__device__ float   g_er[N_NODES * HEADS];
__device__ int     g_deg[N_NODES];
__device__ int     g_off[N_NODES + 1];
__device__ int     g_cur[N_NODES];
__device__ int     g_ssrc[E_NUM];
__device__ float4  g_se4[E_NUM];                   // per-edge logits, [p][h] packed
__device__ int     g_bsum[SCAN_NB];

// ---------------- helpers --------------------------------------------------
__device__ __forceinline__ void mma_f16(float c[4], const unsigned a[4],
                                        const unsigned b[2]) {
    asm volatile(
        "mma.sync.aligned.m16n8k16.row.col.f32.f16.f16.f32 "
        "{%0,%1,%2,%3}, {%4,%5,%6,%7}, {%8,%9}, {%0,%1,%2,%3};"
        : "+f"(c[0]), "+f"(c[1]), "+f"(c[2]), "+f"(c[3])
        : "r"(a[0]), "r"(a[1]), "r"(a[2]), "r"(a[3]), "r"(b[0]), "r"(b[1]));
}

__device__ __forceinline__ uint4 pack8h(float4 lo, float4 hi) {
    __half2 h0 = __floats2half2_rn(lo.x, lo.y);
    __half2 h1 = __floats2half2_rn(lo.z, lo.w);
    __half2 h2 = __floats2half2_rn(hi.x, hi.y);
    __half2 h3 = __floats2half2_rn(hi.z, hi.w);
    uint4 r;
    r.x = *(unsigned*)&h0;
    r.y = *(unsigned*)&h1;
    r.z = *(unsigned*)&h2;
    r.w = *(unsigned*)&h3;
    return r;
}

// ---------------- 1) fp16 MMA GEMM, double-buffered, fp16 output -----------
// M=50000, N=256, K=256. Block tile 128x128, K-tile 16, reg-prefetch pipeline.
// 8 warps: warp_m in {0,1} (64 rows), warp_n in {0..3} (32 cols).
// smem rows padded to 24 halves: fragment LDS bank = (12*row + tig) % 32,
// all-distinct across a warp -> conflict-free.
#define KPAD 24
__global__ __launch_bounds__(256, 2)
void gemm_f16_kernel(const float* __restrict__ A, const float* __restrict__ W) {
    __shared__ __half As[2][128][KPAD];
    __shared__ __half Bs[2][128][KPAD];
    const int tid  = threadIdx.x;
    const int bm   = blockIdx.y, bn = blockIdx.x;
    const int lane = tid & 31;
    const int warp = tid >> 5;
    const int warp_m = warp & 1;
    const int warp_n = warp >> 1;
    const int gid = lane >> 2;          // 0..7
    const int tig = lane & 3;           // 0..3

    const int lrow = tid >> 1;          // 0..127 (tile row this thread stages)
    const int lseg = (tid & 1) * 8;     // k sub-offset 0 or 8
    const int arow = bm * 128 + lrow;
    const bool aok = arow < N_NODES;
    const float* aptr = A + (size_t)(aok ? arow : 0) * IN_F + lseg;
    const float* bptr = W + (size_t)(bn * 128 + lrow) * IN_F + lseg;

    float acc[4][4][4];
    #pragma unroll
    for (int im = 0; im < 4; im++)
        #pragma unroll
        for (int in = 0; in < 4; in++)
            #pragma unroll
            for (int q = 0; q < 4; q++) acc[im][in][q] = 0.f;

    float4 ra0, ra1, rb0, rb1;
    // prefetch k-tile 0
    ra0 = *(const float4*)(aptr);    ra1 = *(const float4*)(aptr + 4);
    rb0 = *(const float4*)(bptr);    rb1 = *(const float4*)(bptr + 4);
    if (!aok) { ra0 = make_float4(0.f,0.f,0.f,0.f); ra1 = ra0; }
    *(uint4*)&As[0][lrow][lseg] = pack8h(ra0, ra1);
    *(uint4*)&Bs[0][lrow][lseg] = pack8h(rb0, rb1);
    __syncthreads();

    const int NKT = IN_F / 16;   // 16
    for (int kt = 0; kt < NKT; kt++) {
        const int buf = kt & 1;
        // prefetch next k-tile into registers (LDG in flight during MMAs)
        if (kt + 1 < NKT) {
            const float* ap = aptr + (kt + 1) * 16;
            const float* bp = bptr + (kt + 1) * 16;
            ra0 = *(const float4*)(ap);  ra1 = *(const float4*)(ap + 4);
            rb0 = *(const float4*)(bp);  rb1 = *(const float4*)(bp + 4);
            if (!aok) { ra0 = make_float4(0.f,0.f,0.f,0.f); ra1 = ra0; }
        }
        // compute current tile: one k16 step per mma
        {
            unsigned af[4][4], bf[4][2];
            #pragma unroll
            for (int im = 0; im < 4; im++) {
                int m0 = warp_m * 64 + im * 16;
                af[im][0] = *(const unsigned*)&As[buf][m0 + gid    ][2 * tig    ];
                af[im][1] = *(const unsigned*)&As[buf][m0 + gid + 8][2 * tig    ];
                af[im][2] = *(const unsigned*)&As[buf][m0 + gid    ][2 * tig + 8];
                af[im][3] = *(const unsigned*)&As[buf][m0 + gid + 8][2 * tig + 8];
            }
            #pragma unroll
            for (int in = 0; in < 4; in++) {
                int n0 = warp_n * 32 + in * 8;
                bf[in][0] = *(const unsigned*)&Bs[buf][n0 + gid][2 * tig    ];
                bf[in][1] = *(const unsigned*)&Bs[buf][n0 + gid][2 * tig + 8];
            }
            #pragma unroll
            for (int im = 0; im < 4; im++)
                #pragma unroll
                for (int in = 0; in < 4; in++)
                    mma_f16(acc[im][in], af[im], bf[in]);
        }
        // stage next tile into the other buffer
        if (kt + 1 < NKT) {
            *(uint4*)&As[buf ^ 1][lrow][lseg] = pack8h(ra0, ra1);
            *(uint4*)&Bs[buf ^ 1][lrow][lseg] = pack8h(rb0, rb1);
            __syncthreads();
        }
    }

    // epilogue: fp16 (RTE) stores; c0,c1 -> (row gid, 2tig..+1), c2,c3 -> row gid+8
    #pragma unroll
    for (int im = 0; im < 4; im++) {
        int r0 = bm * 128 + warp_m * 64 + im * 16 + gid;
        #pragma unroll
        for (int in = 0; in < 4; in++) {
            int cb = bn * 128 + warp_n * 32 + in * 8 + tig * 2;
            if (r0 < N_NODES)
                *(__half2*)(g_fth + (size_t)r0 * HD + cb) =
                    __floats2half2_rn(acc[im][in][0], acc[im][in][1]);
            if (r0 + 8 < N_NODES)
                *(__half2*)(g_fth + (size_t)(r0 + 8) * HD + cb) =
                    __floats2half2_rn(acc[im][in][2], acc[im][in][3]);
        }
    }
}

// ---------------- 2) el/er: warp per node, lane owns 8 cols ----------------
__global__ void elr_kernel(const float* __restrict__ al, const float* __restrict__ ar) {
    int g = blockIdx.x * blockDim.x + threadIdx.x;
    int node = g >> 5;
    if (node >= N_NODES) return;
    int lane = g & 31;
    int h = lane >> 3, q = lane & 7;

    uint4 v = *(const uint4*)(g_fth + (size_t)node * HD + lane * 8);
    const __half2* hv = (const __half2*)&v;
    const float* alp = al + h * DHEAD + q * 8;
    const float* arp = ar + h * DHEAD + q * 8;
    float4 l0 = *(const float4*)(alp), l1 = *(const float4*)(alp + 4);
    float4 r0 = *(const float4*)(arp), r1 = *(const float4*)(arp + 4);
    float f[8];
    #pragma unroll
    for (int j = 0; j < 4; j++) {
        float2 p = __half22float2(hv[j]);
        f[2 * j] = p.x; f[2 * j + 1] = p.y;
    }
    float dl = f[0]*l0.x + f[1]*l0.y + f[2]*l0.z + f[3]*l0.w
             + f[4]*l1.x + f[5]*l1.y + f[6]*l1.z + f[7]*l1.w;
    float dr = f[0]*r0.x + f[1]*r0.y + f[2]*r0.z + f[3]*r0.w
             + f[4]*r1.x + f[5]*r1.y + f[6]*r1.z + f[7]*r1.w;
    #pragma unroll
    for (int o = 4; o; o >>= 1) {
        dl += __shfl_xor_sync(0xffffffff, dl, o);
        dr += __shfl_xor_sync(0xffffffff, dr, o);
    }
    if (q == 0) {
        g_el[node * HEADS + h] = dl;
        g_er[node * HEADS + h] = dr;
    }
}

// ---------------- 3) CSR build ---------------------------------------------
__global__ void zero_deg_kernel() {
    int i = blockIdx.x * blockDim.x + threadIdx.x;
    if (i < N_NODES) g_deg[i] = 0;
}

__global__ void hist_kernel(const int* __restrict__ dst) {
    int e = blockIdx.x * blockDim.x + threadIdx.x;
    if (e < E_NUM) atomicAdd(&g_deg[dst[e]], 1);
}

__global__ __launch_bounds__(SCAN_B)
void scan1_kernel() {
    __shared__ int ws[32];
    int tid = threadIdx.x, lane = tid & 31, wid = tid >> 5;
    int i = blockIdx.x * SCAN_B + tid;
    int v = (i < N_NODES) ? g_deg[i] : 0;
    int x = v;
    #pragma unroll
    for (int o = 1; o < 32; o <<= 1) {
        int t = __shfl_up_sync(0xffffffff, x, o);
        if (lane >= o) x += t;
    }
    if (lane == 31) ws[wid] = x;
    __syncthreads();
    if (wid == 0) {
        int y = ws[lane];
        #pragma unroll
        for (int o = 1; o < 32; o <<= 1) {
            int t = __shfl_up_sync(0xffffffff, y, o);
            if (lane >= o) y += t;
        }
        ws[lane] = y;
    }
    __syncthreads();
    int base = (wid == 0) ? 0 : ws[wid - 1];
    if (i < N_NODES) g_off[i] = base + x - v;
    if (tid == 0) g_bsum[blockIdx.x] = ws[31];
}

__global__ void scan2_kernel() {
    __shared__ int ws[2];
    int tid = threadIdx.x, lane = tid & 31, wid = tid >> 5;
    int v = (tid < SCAN_NB) ? g_bsum[tid] : 0;
    int x = v;
    #pragma unroll
    for (int o = 1; o < 32; o <<= 1) {
        int t = __shfl_up_sync(0xffffffff, x, o);
        if (lane >= o) x += t;
    }
    if (lane == 31) ws[wid] = x;
    __syncthreads();
    int base = (wid == 1) ? ws[0] : 0;
    if (tid < SCAN_NB) g_bsum[tid] = base + x - v;
}

__global__ void scan3_kernel() {
    int i = blockIdx.x * blockDim.x + threadIdx.x;
    if (i < N_NODES) {
        int off = g_off[i] + g_bsum[i >> 10];
        g_off[i] = off;
        g_cur[i] = off;
    }
    if (i == 0) g_off[N_NODES] = E_NUM;
}

__global__ void scatter_kernel(const int* __restrict__ src, const int* __restrict__ dst,
                               const int* __restrict__ ef, const float* __restrict__ ew) {
    int e = blockIdx.x * blockDim.x + threadIdx.x;
    if (e >= E_NUM) return;
    int s = src[e], d = dst[e], t = ef[e] - 1;
    int p = atomicAdd(&g_cur[d], 1);
    g_ssrc[p] = s;
    float v[HEADS];
    #pragma unroll
    for (int h = 0; h < HEADS; h++) {
        float w = ew[t * HEADS + h] * ALPHA_C;
        w = (w >= 0.f) ? w : SLOPE_EW * w;
        float x = (g_el[s * HEADS + h] + g_er[d * HEADS + h]) * w;
        v[h] = (x >= 0.f) ? x : SLOPE_ATTN * x;
    }
    g_se4[p] = make_float4(v[0], v[1], v[2], v[3]);
}

// ---------------- 4) warp per node: softmax + weighted gather, all heads ---
__global__ __launch_bounds__(256)
void agg_kernel(float* __restrict__ out) {
    int n = (blockIdx.x * blockDim.x + threadIdx.x) >> 5;
    int lane = threadIdx.x & 31;
    if (n >= N_NODES) return;
    int h = lane >> 3, q = lane & 7;
    int s0 = g_off[n], s1 = g_off[n + 1];
    const float* se = (const float*)g_se4;   // logit of edge k, head h at [k*4+h]

    // pass 1: per-head max, 8-wide strided + 3-step reduce within head group
    float m = -INFINITY;
    for (int k = s0 + q; k < s1; k += 8) m = fmaxf(m, se[k * 4 + h]);
    #pragma unroll
    for (int o = 4; o; o >>= 1) m = fmaxf(m, __shfl_xor_sync(0xffffffff, m, o));

    // pass 2: exp weights + gather ft[src] (one uint4/lane = 8 halves = full row/warp)
    float sum = 0.f;
    float acc[8];
    #pragma unroll
    for (int j = 0; j < 8; j++) acc[j] = 0.f;
    #pragma unroll 4
    for (int k = s0; k < s1; k++) {
        float wg = __expf(se[k * 4 + h] - m);
        int s = g_ssrc[k];
        uint4 v = *(const uint4*)(g_fth + (size_t)s * HD + lane * 8);
        const __half2* hv = (const __half2*)&v;
        #pragma unroll
        for (int j = 0; j < 4; j++) {
            float2 p = __half22float2(hv[j]);
            acc[2 * j]     += wg * p.x;
            acc[2 * j + 1] += wg * p.y;
        }
        sum += wg;
    }
    float inv = (s1 > s0) ? 1.f / sum : 0.f;
    float* op = out + (size_t)n * HD + lane * 8;
    *(float4*)op       = make_float4(acc[0] * inv, acc[1] * inv, acc[2] * inv, acc[3] * inv);
    *((float4*)op + 1) = make_float4(acc[4] * inv, acc[5] * inv, acc[6] * inv, acc[7] * inv);
}

// ---------------- launch --------------------------------------------------
extern "C" void kernel_launch(void* const* d_in, const int* in_sizes, int n_in,
                              void* d_out, int out_size) {
    const float* feat  = (const float*)d_in[0];
    const int*   src   = (const int*)d_in[1];
    const int*   dst   = (const int*)d_in[2];
    const int*   ef    = (const int*)d_in[3];
    const float* fc_w  = (const float*)d_in[4];
    const float* attnl = (const float*)d_in[5];
    const float* attnr = (const float*)d_in[6];
    const float* ew    = (const float*)d_in[7];
    float* out = (float*)d_out;

    (void)in_sizes; (void)n_in; (void)out_size;

    // 1) GEMM (fp16 tensor-core, double-buffered, fp16 output)
    dim3 ggrid(HD / 128, (N_NODES + 127) / 128);
    gemm_f16_kernel<<<ggrid, 256>>>(feat, fc_w);

    // 2) el / er
    {
        long long tt = (long long)N_NODES * 32;
        elr_kernel<<<(unsigned)((tt + 255) / 256), 256>>>(attnl, attnr);
    }

    // 3) CSR build
    zero_deg_kernel<<<(N_NODES + 255) / 256, 256>>>();
    hist_kernel<<<(E_NUM + 255) / 256, 256>>>(dst);
    scan1_kernel<<<SCAN_NB, SCAN_B>>>();
    scan2_kernel<<<1, 64>>>();
    scan3_kernel<<<(N_NODES + 255) / 256, 256>>>();
    scatter_kernel<<<(E_NUM + 255) / 256, 256>>>(src, dst, ef, ew);

    // 4) softmax + aggregation (warp per node, all heads)
    {
        long long tt = (long long)N_NODES * 32;
        agg_kernel<<<(unsigned)((tt + 255) / 256), 256>>>(out);
    }
}